// round 1
// baseline (speedup 1.0000x reference)
#include <cuda_runtime.h>

#define BB 4
#define TK 512
#define TQ 512
#define KS 256     // KEYSIZE == QUESIZE
#define H  128
#define VS 256
#define KR 8       // k-rows per block in main kernel
#define HC 8       // h chunk staged in smem

// scratch for projections (allocation-free rule: __device__ globals)
__device__ float g_kp[BB * TK * H];
__device__ float g_qp[BB * TQ * H];

// ---------------------------------------------------------------------------
// Projection: out = X @ W + b   (2048x256 @ 256x128)
// blocks 0..127 -> kp (key, W_k, b_k), 128..255 -> qp (que, W_q, b_q)
// 16 rows per block, 128 threads (one per output h)
// ---------------------------------------------------------------------------
__global__ __launch_bounds__(128) void proj_kernel(
    const float* __restrict__ key, const float* __restrict__ que,
    const float* __restrict__ W_k, const float* __restrict__ b_k,
    const float* __restrict__ W_q, const float* __restrict__ b_q)
{
    __shared__ float Ws[32][H];
    __shared__ float Xs[16][32];

    const int tid = threadIdx.x;           // 0..127 == output h
    const bool isQ = (blockIdx.x >= 128);
    const int row0 = (blockIdx.x & 127) * 16;
    const float* __restrict__ X = isQ ? que : key;
    const float* __restrict__ W = isQ ? W_q : W_k;
    const float* __restrict__ bias = isQ ? b_q : b_k;
    float* __restrict__ out = isQ ? g_qp : g_kp;

    float acc[16];
#pragma unroll
    for (int r = 0; r < 16; r++) acc[r] = 0.f;

    for (int kc = 0; kc < KS; kc += 32) {
#pragma unroll
        for (int i = 0; i < 32; i++)
            Ws[i][tid] = W[(kc + i) * H + tid];
#pragma unroll
        for (int i = 0; i < 4; i++) {
            int idx = i * 128 + tid;
            int r = idx >> 5, c = idx & 31;
            Xs[r][c] = X[(row0 + r) * KS + kc + c];
        }
        __syncthreads();
#pragma unroll
        for (int c = 0; c < 32; c++) {
            float w = Ws[c][tid];
#pragma unroll
            for (int r = 0; r < 16; r++)
                acc[r] = fmaf(Xs[r][c], w, acc[r]);
        }
        __syncthreads();
    }
    const float bb = bias[tid];
#pragma unroll
    for (int r = 0; r < 16; r++)
        out[(row0 + r) * H + tid] = acc[r] + bb;
}

// ---------------------------------------------------------------------------
// Fused scores + masked softmax + attn@value.
// One block = 8 k-rows of one batch. 256 blocks, 256 threads.
// ---------------------------------------------------------------------------
__global__ __launch_bounds__(256) void attn_kernel(
    const float* __restrict__ value,
    const float* __restrict__ w_v,
    const int*   __restrict__ valid_lens,
    float*       __restrict__ out)
{
    __shared__ float qpS[TQ * (HC + 1)];   // [512][9]  ~18.4KB
    __shared__ float kpS[KR][H];           // 4KB
    __shared__ float wvS[H];
    __shared__ float attnS[KR][TQ];        // 16KB: scores -> attn
    __shared__ int   vlS[KR];

    const int tid = threadIdx.x;           // 0..255
    const int bid = blockIdx.x;            // 0..255
    const int b   = bid >> 6;              // 64 blocks per batch
    const int kt0 = (bid & 63) * KR;

    // stage kp rows / w_v / valid_lens
#pragma unroll
    for (int i = 0; i < 4; i++) {
        int idx = i * 256 + tid;           // 0..1023
        int kr = idx >> 7, h = idx & 127;
        kpS[kr][h] = g_kp[(b * TK + kt0 + kr) * H + h];
    }
    if (tid < H)  wvS[tid] = w_v[tid];
    if (tid < KR) vlS[tid] = valid_lens[b * TK + kt0 + tid];

    // ---- phase 1: scores, thread computes 4x4 (kr x t) tile ----
    const int g_kr = tid >> 7;             // 0..1   (kr = g_kr + 2i)
    const int g_t  = tid & 127;            // 0..127 (t  = g_t + 128j)

    float acc[4][4];
#pragma unroll
    for (int i = 0; i < 4; i++)
#pragma unroll
        for (int j = 0; j < 4; j++) acc[i][j] = 0.f;

    for (int hb = 0; hb < H; hb += HC) {
        __syncthreads();                   // protect qpS reuse
        // load qp chunk [512][8] as float4, store scalar (pad=9 stays conflict-free)
#pragma unroll
        for (int i = 0; i < 4; i++) {
            int idx = i * 256 + tid;       // 0..1023
            int t = idx >> 1, c = idx & 1;
            const float4 v = *(const float4*)&g_qp[(b * TQ + t) * H + hb + c * 4];
            float* d = &qpS[t * (HC + 1) + c * 4];
            d[0] = v.x; d[1] = v.y; d[2] = v.z; d[3] = v.w;
        }
        __syncthreads();
#pragma unroll
        for (int hl = 0; hl < HC; hl++) {
            const float wv = wvS[hb + hl];
            float kv[4], qv[4];
#pragma unroll
            for (int i = 0; i < 4; i++) kv[i] = kpS[g_kr + 2 * i][hb + hl];
#pragma unroll
            for (int j = 0; j < 4; j++) qv[j] = qpS[(g_t + 128 * j) * (HC + 1) + hl];
#pragma unroll
            for (int i = 0; i < 4; i++)
#pragma unroll
                for (int j = 0; j < 4; j++) {
                    float x = kv[i] + qv[j];
                    float th;
                    asm("tanh.approx.f32 %0, %1;" : "=f"(th) : "f"(x));
                    acc[i][j] = fmaf(th, wv, acc[i][j]);
                }
        }
    }
    // write scores (b_v omitted: softmax is shift-invariant)
#pragma unroll
    for (int i = 0; i < 4; i++)
#pragma unroll
        for (int j = 0; j < 4; j++)
            attnS[g_kr + 2 * i][g_t + 128 * j] = acc[i][j];
    __syncthreads();

    // ---- phase 2: masked softmax, warp w owns row w ----
    {
        const int wid = tid >> 5, lane = tid & 31;
        const int row = wid;
        const int vl  = vlS[row];
        float m = -1e30f;
        for (int t = lane; t < TQ; t += 32) {
            float s = attnS[row][t];
            if (t < vl) m = fmaxf(m, s);
        }
#pragma unroll
        for (int o = 16; o; o >>= 1) m = fmaxf(m, __shfl_xor_sync(0xffffffffu, m, o));
        float sum = 0.f;
        for (int t = lane; t < TQ; t += 32) {
            float e = (t < vl) ? __expf(attnS[row][t] - m) : 0.f;
            attnS[row][t] = e;
            sum += e;
        }
#pragma unroll
        for (int o = 16; o; o >>= 1) sum += __shfl_xor_sync(0xffffffffu, sum, o);
        const float inv = 1.f / sum;
        for (int t = lane; t < TQ; t += 32) attnS[row][t] *= inv;
    }
    __syncthreads();

    // ---- phase 3: out[kr][v] = sum_t attn[kr][t] * value[b][t][v] ----
    // thread owns v4 = tid&63 (4 v cols) for kr pair {2*krp, 2*krp+1}
    {
        const int v4  = tid & 63;
        const int krp = tid >> 6;          // 0..3, constant within a warp
        float4 o0 = make_float4(0.f, 0.f, 0.f, 0.f);
        float4 o1 = make_float4(0.f, 0.f, 0.f, 0.f);
        const float4* __restrict__ val4 =
            (const float4*)&value[(size_t)b * TQ * VS];
#pragma unroll 4
        for (int t = 0; t < TQ; t++) {
            const float4 v = val4[t * (VS / 4) + v4];
            const float a0 = attnS[2 * krp][t];
            const float a1 = attnS[2 * krp + 1][t];
            o0.x = fmaf(a0, v.x, o0.x); o0.y = fmaf(a0, v.y, o0.y);
            o0.z = fmaf(a0, v.z, o0.z); o0.w = fmaf(a0, v.w, o0.w);
            o1.x = fmaf(a1, v.x, o1.x); o1.y = fmaf(a1, v.y, o1.y);
            o1.z = fmaf(a1, v.z, o1.z); o1.w = fmaf(a1, v.w, o1.w);
        }
        const int r0 = (b * TK + kt0 + 2 * krp) * VS + v4 * 4;
        *(float4*)&out[r0]      = o0;
        *(float4*)&out[r0 + VS] = o1;
    }
}

// ---------------------------------------------------------------------------
extern "C" void kernel_launch(void* const* d_in, const int* in_sizes, int n_in,
                              void* d_out, int out_size)
{
    const float* key        = (const float*)d_in[0];
    const float* que        = (const float*)d_in[1];
    const float* value      = (const float*)d_in[2];
    const float* W_k        = (const float*)d_in[3];
    const float* b_k        = (const float*)d_in[4];
    const float* W_q        = (const float*)d_in[5];
    const float* b_q        = (const float*)d_in[6];
    const float* w_v        = (const float*)d_in[7];
    // d_in[8] = b_v: unused (softmax shift-invariant)
    const int*   valid_lens = (const int*)d_in[9];
    float* out = (float*)d_out;

    proj_kernel<<<256, 128>>>(key, que, W_k, b_k, W_q, b_q);
    attn_kernel<<<BB * TK / KR, 256>>>(value, w_v, valid_lens, out);
}

// round 2
// speedup vs baseline: 1.1289x; 1.1289x over previous
#include <cuda_runtime.h>

#define BB 4
#define TK 512
#define TQ 512
#define KS 256     // KEYSIZE == QUESIZE
#define H  128
#define VS 256
#define KR 8       // k-rows per block in main kernel
#define HC 8       // h chunk staged in smem

// scratch for projections (allocation-free rule: __device__ globals)
__device__ float g_kp[BB * TK * H];
__device__ float g_qp[BB * TQ * H];

// ---------------------------------------------------------------------------
// Projection: out = X @ W + b   (2048x256 @ 256x128)
// blocks 0..127 -> kp (key, W_k, b_k), 128..255 -> qp (que, W_q, b_q)
// 16 rows per block, 128 threads (one per output h)
// ---------------------------------------------------------------------------
__global__ __launch_bounds__(128) void proj_kernel(
    const float* __restrict__ key, const float* __restrict__ que,
    const float* __restrict__ W_k, const float* __restrict__ b_k,
    const float* __restrict__ W_q, const float* __restrict__ b_q)
{
    __shared__ float Ws[32][H];
    __shared__ float Xs[16][32];

    const int tid = threadIdx.x;           // 0..127 == output h
    const bool isQ = (blockIdx.x >= 128);
    const int row0 = (blockIdx.x & 127) * 16;
    const float* __restrict__ X = isQ ? que : key;
    const float* __restrict__ W = isQ ? W_q : W_k;
    const float* __restrict__ bias = isQ ? b_q : b_k;
    float* __restrict__ out = isQ ? g_qp : g_kp;

    float acc[16];
#pragma unroll
    for (int r = 0; r < 16; r++) acc[r] = 0.f;

    for (int kc = 0; kc < KS; kc += 32) {
#pragma unroll
        for (int i = 0; i < 32; i++)
            Ws[i][tid] = W[(kc + i) * H + tid];
#pragma unroll
        for (int i = 0; i < 4; i++) {
            int idx = i * 128 + tid;
            int r = idx >> 5, c = idx & 31;
            Xs[r][c] = X[(row0 + r) * KS + kc + c];
        }
        __syncthreads();
#pragma unroll
        for (int c = 0; c < 32; c++) {
            float w = Ws[c][tid];
#pragma unroll
            for (int r = 0; r < 16; r++)
                acc[r] = fmaf(Xs[r][c], w, acc[r]);
        }
        __syncthreads();
    }
    const float bb = bias[tid];
#pragma unroll
    for (int r = 0; r < 16; r++)
        out[(row0 + r) * H + tid] = acc[r] + bb;
}

// ---------------------------------------------------------------------------
// Fused scores + masked softmax + attn@value.
// One block = 8 k-rows of one batch. 256 blocks, 256 threads.
// Phase 1 is software-pipelined: next qp chunk prefetched into registers
// while computing on the current smem-resident chunk.
// ---------------------------------------------------------------------------
__global__ __launch_bounds__(256) void attn_kernel(
    const float* __restrict__ value,
    const float* __restrict__ w_v,
    const int*   __restrict__ valid_lens,
    float*       __restrict__ out)
{
    __shared__ float qpS[TQ * (HC + 1)];   // [512][9]  ~18.4KB
    __shared__ float kpS[KR][H];           // 4KB
    __shared__ float wvS[H];
    __shared__ float attnS[KR][TQ];        // 16KB: scores -> attn -> phase3 partials
    __shared__ int   vlS[KR];

    const int tid = threadIdx.x;           // 0..255
    const int bid = blockIdx.x;            // 0..255
    const int b   = bid >> 6;              // 64 blocks per batch
    const int kt0 = (bid & 63) * KR;

    // stage kp rows / w_v / valid_lens
#pragma unroll
    for (int i = 0; i < 4; i++) {
        int idx = i * 256 + tid;           // 0..1023
        int kr = idx >> 7, h = idx & 127;
        kpS[kr][h] = g_kp[(b * TK + kt0 + kr) * H + h];
    }
    if (tid < H)  wvS[tid] = w_v[tid];
    if (tid < KR) vlS[tid] = valid_lens[b * TK + kt0 + tid];

    // ---- phase 1: scores, thread computes 4x4 (kr x t) tile ----
    const int g_kr = tid >> 7;             // 0..1   (kr = g_kr + 2i)
    const int g_t  = tid & 127;            // 0..127 (t  = g_t + 128j)
    const int ld_t = tid >> 1;             // chunk loader: this thread's t rows
    const int ld_c = (tid & 1) * 4;        // h sub-offset (0 or 4)

    float acc[4][4];
#pragma unroll
    for (int i = 0; i < 4; i++)
#pragma unroll
        for (int j = 0; j < 4; j++) acc[i][j] = 0.f;

    const float* __restrict__ qpBase = &g_qp[(size_t)b * TQ * H];

    // prologue: prefetch chunk 0 into registers
    float4 pre[4];
#pragma unroll
    for (int i = 0; i < 4; i++)
        pre[i] = *(const float4*)&qpBase[(ld_t + 128 * i) * H + ld_c];

    for (int hb = 0; hb < H; hb += HC) {
        __syncthreads();                   // previous chunk fully consumed
        // commit prefetched chunk to smem
#pragma unroll
        for (int i = 0; i < 4; i++) {
            float* d = &qpS[(ld_t + 128 * i) * (HC + 1) + ld_c];
            d[0] = pre[i].x; d[1] = pre[i].y; d[2] = pre[i].z; d[3] = pre[i].w;
        }
        // prefetch next chunk (lands while we compute on this one)
        if (hb + HC < H) {
#pragma unroll
            for (int i = 0; i < 4; i++)
                pre[i] = *(const float4*)&qpBase[(ld_t + 128 * i) * H + hb + HC + ld_c];
        }
        __syncthreads();
#pragma unroll
        for (int hl = 0; hl < HC; hl++) {
            const float wv = wvS[hb + hl];
            float kv[4], qv[4];
#pragma unroll
            for (int i = 0; i < 4; i++) kv[i] = kpS[g_kr + 2 * i][hb + hl];
#pragma unroll
            for (int j = 0; j < 4; j++) qv[j] = qpS[(g_t + 128 * j) * (HC + 1) + hl];
#pragma unroll
            for (int i = 0; i < 4; i++)
#pragma unroll
                for (int j = 0; j < 4; j++) {
                    float x = kv[i] + qv[j];
                    float th;
                    asm("tanh.approx.f32 %0, %1;" : "=f"(th) : "f"(x));
                    acc[i][j] = fmaf(th, wv, acc[i][j]);
                }
        }
    }
    // write scores (b_v omitted: softmax is shift-invariant)
#pragma unroll
    for (int i = 0; i < 4; i++)
#pragma unroll
        for (int j = 0; j < 4; j++)
            attnS[g_kr + 2 * i][g_t + 128 * j] = acc[i][j];
    __syncthreads();

    // ---- phase 2: masked softmax, warp w owns row w ----
    {
        const int wid = tid >> 5, lane = tid & 31;
        const int row = wid;
        const int vl  = vlS[row];
        float m = -1e30f;
        for (int t = lane; t < TQ; t += 32) {
            float s = attnS[row][t];
            if (t < vl) m = fmaxf(m, s);
        }
#pragma unroll
        for (int o = 16; o; o >>= 1) m = fmaxf(m, __shfl_xor_sync(0xffffffffu, m, o));
        float sum = 0.f;
        for (int t = lane; t < TQ; t += 32) {
            float e = (t < vl) ? __expf(attnS[row][t] - m) : 0.f;
            attnS[row][t] = e;
            sum += e;
        }
#pragma unroll
        for (int o = 16; o; o >>= 1) sum += __shfl_xor_sync(0xffffffffu, sum, o);
        const float inv = 1.f / sum;
        for (int t = lane; t < TQ; t += 32) attnS[row][t] *= inv;
    }
    __syncthreads();

    // ---- phase 3: out[kr][v] = sum_t attn[kr][t] * value[b][t][v] ----
    // thread = (v4, krq, th): 4 k-rows per value read, t split in 2 halves.
    {
        const int v4  = tid & 63;          // float4 column 0..63
        const int grp = tid >> 6;          // 0..3
        const int krq = grp & 1;           // kr base = krq*4
        const int th  = grp >> 1;          // t half
        const int t0  = th * (TQ / 2);

        float4 o[4];
#pragma unroll
        for (int i = 0; i < 4; i++) o[i] = make_float4(0.f, 0.f, 0.f, 0.f);

        const float4* __restrict__ val4 =
            (const float4*)&value[(size_t)b * TQ * VS];
#pragma unroll 4
        for (int t = t0; t < t0 + TQ / 2; t++) {
            const float4 v = val4[t * (VS / 4) + v4];
#pragma unroll
            for (int i = 0; i < 4; i++) {
                const float a = attnS[krq * 4 + i][t];
                o[i].x = fmaf(a, v.x, o[i].x);
                o[i].y = fmaf(a, v.y, o[i].y);
                o[i].z = fmaf(a, v.z, o[i].z);
                o[i].w = fmaf(a, v.w, o[i].w);
            }
        }
        __syncthreads();                   // everyone done READING attnS
        // partials into the attnS bytes: part[(th*8 + kr)*64 + v4]
        float4* part = (float4*)&attnS[0][0];   // 1024 float4 = 16KB
#pragma unroll
        for (int i = 0; i < 4; i++)
            part[(th * 8 + krq * 4 + i) * 64 + v4] = o[i];
        __syncthreads();
        // reduce the two t-halves and store
#pragma unroll
        for (int s = 0; s < 2; s++) {
            int idx = tid + s * 256;       // 0..511
            int kr = idx >> 6, vv = idx & 63;
            float4 a = part[kr * 64 + vv];
            float4 c = part[(8 + kr) * 64 + vv];
            float4 r = make_float4(a.x + c.x, a.y + c.y, a.z + c.z, a.w + c.w);
            *(float4*)&out[(size_t)(b * TK + kt0 + kr) * VS + vv * 4] = r;
        }
    }
}

// ---------------------------------------------------------------------------
extern "C" void kernel_launch(void* const* d_in, const int* in_sizes, int n_in,
                              void* d_out, int out_size)
{
    const float* key        = (const float*)d_in[0];
    const float* que        = (const float*)d_in[1];
    const float* value      = (const float*)d_in[2];
    const float* W_k        = (const float*)d_in[3];
    const float* b_k        = (const float*)d_in[4];
    const float* W_q        = (const float*)d_in[5];
    const float* b_q        = (const float*)d_in[6];
    const float* w_v        = (const float*)d_in[7];
    // d_in[8] = b_v: unused (softmax shift-invariant)
    const int*   valid_lens = (const int*)d_in[9];
    float* out = (float*)d_out;

    proj_kernel<<<256, 128>>>(key, que, W_k, b_k, W_q, b_q);
    attn_kernel<<<BB * TK / KR, 256>>>(value, w_v, valid_lens, out);
}

// round 4
// speedup vs baseline: 1.2673x; 1.1226x over previous
#include <cuda_runtime.h>

#define BB 4
#define TK 512
#define TQ 512
#define KS 256     // KEYSIZE == QUESIZE
#define H  128
#define VS 256
#define KR 8       // k-rows per block in main kernel
#define HC 8       // h chunk staged in smem
#define QP 9       // qpS row stride (odd => conflict-free scalar LDS)

// dynamic smem layout (bytes)
#define SM_QP    0                         // 2 * TQ * QP * 4 = 36864
#define SM_KP    36864                     // KR * H * 4      = 4096
#define SM_WV    40960                     // H * 4           = 512
#define SM_ATTN  41472                     // KR * TQ * 4     = 16384
#define SM_VL    57856                     // KR * 4          = 32
#define SM_TOTAL 57888

// scratch for projections (allocation-free rule: __device__ globals)
__device__ float g_kp[BB * TK * H];
__device__ float g_qp[BB * TQ * H];

// ---- f32x2 packed helpers (Blackwell) -------------------------------------
__device__ __forceinline__ unsigned long long pk2(float x, float y) {
    unsigned long long r;
    asm("mov.b64 %0, {%1,%2};" : "=l"(r) : "f"(x), "f"(y));
    return r;
}
__device__ __forceinline__ void upk2(unsigned long long v, float& x, float& y) {
    asm("mov.b64 {%0,%1}, %2;" : "=f"(x), "=f"(y) : "l"(v));
}
__device__ __forceinline__ unsigned long long add2(unsigned long long a,
                                                   unsigned long long b) {
    unsigned long long r;
    asm("add.rn.f32x2 %0, %1, %2;" : "=l"(r) : "l"(a), "l"(b));
    return r;
}
__device__ __forceinline__ void fma2(unsigned long long& d,
                                     unsigned long long a,
                                     unsigned long long b) {
    asm("fma.rn.f32x2 %0, %1, %2, %0;" : "+l"(d) : "l"(a), "l"(b));
}

// ---------------------------------------------------------------------------
// Projection: out = X @ W + b   (2048x256 @ 256x128)
// blocks 0..127 -> kp (key, W_k, b_k), 128..255 -> qp (que, W_q, b_q)
// ---------------------------------------------------------------------------
__global__ __launch_bounds__(128) void proj_kernel(
    const float* __restrict__ key, const float* __restrict__ que,
    const float* __restrict__ W_k, const float* __restrict__ b_k,
    const float* __restrict__ W_q, const float* __restrict__ b_q)
{
    __shared__ float Ws[32][H];
    __shared__ float Xs[16][32];

    const int tid = threadIdx.x;           // 0..127 == output h
    const bool isQ = (blockIdx.x >= 128);
    const int row0 = (blockIdx.x & 127) * 16;
    const float* __restrict__ X = isQ ? que : key;
    const float* __restrict__ W = isQ ? W_q : W_k;
    const float* __restrict__ bias = isQ ? b_q : b_k;
    float* __restrict__ out = isQ ? g_qp : g_kp;

    float acc[16];
#pragma unroll
    for (int r = 0; r < 16; r++) acc[r] = 0.f;

    for (int kc = 0; kc < KS; kc += 32) {
#pragma unroll
        for (int i = 0; i < 32; i++)
            Ws[i][tid] = W[(kc + i) * H + tid];
#pragma unroll
        for (int i = 0; i < 4; i++) {
            int idx = i * 128 + tid;
            int r = idx >> 5, c = idx & 31;
            Xs[r][c] = X[(row0 + r) * KS + kc + c];
        }
        __syncthreads();
#pragma unroll
        for (int c = 0; c < 32; c++) {
            float w = Ws[c][tid];
#pragma unroll
            for (int r = 0; r < 16; r++)
                acc[r] = fmaf(Xs[r][c], w, acc[r]);
        }
        __syncthreads();
    }
    const float bb = bias[tid];
#pragma unroll
    for (int r = 0; r < 16; r++)
        out[(row0 + r) * H + tid] = acc[r] + bb;
}

// ---------------------------------------------------------------------------
// Fused scores + masked softmax + attn@value.
// One block = 8 k-rows of one batch. 256 blocks, 512 threads (16 warps).
// qpS double-buffered: one barrier per h-chunk. Dynamic smem (57.9KB).
// ---------------------------------------------------------------------------
__global__ __launch_bounds__(512, 2) void attn_kernel(
    const float* __restrict__ value,
    const float* __restrict__ w_v,
    const int*   __restrict__ valid_lens,
    float*       __restrict__ out)
{
    extern __shared__ __align__(16) char smem[];
    float* qpS0  = (float*)(smem + SM_QP);              // [2][TQ*QP]
    float* qpS1  = qpS0 + TQ * QP;
    float (*kpS)[H]  = (float (*)[H])(smem + SM_KP);    // [KR][H]
    float* wvS   = (float*)(smem + SM_WV);              // [H]
    float (*attnS)[TQ] = (float (*)[TQ])(smem + SM_ATTN); // [KR][TQ]
    int*   vlS   = (int*)(smem + SM_VL);                // [KR]

    const int tid = threadIdx.x;           // 0..511
    const int bid = blockIdx.x;            // 0..255
    const int b   = bid >> 6;
    const int kt0 = (bid & 63) * KR;

    // stage kp rows / w_v / valid_lens
#pragma unroll
    for (int i = 0; i < 2; i++) {
        int idx = i * 512 + tid;           // 0..1023
        int kr = idx >> 7, h = idx & 127;
        kpS[kr][h] = g_kp[(b * TK + kt0 + kr) * H + h];
    }
    if (tid < H)  wvS[tid] = w_v[tid];
    if (tid < KR) vlS[tid] = valid_lens[b * TK + kt0 + tid];

    // ---- phase 1: scores; thread computes 2x4 (kr x t) tile ----
    const int g_kr = tid >> 7;             // 0..3   (kr = g_kr + 4i)
    const int g_t  = tid & 127;            // t = g_t + 128j

    float acc_lo, acc_hi;
    unsigned long long acc[2][4];
#pragma unroll
    for (int i = 0; i < 2; i++)
#pragma unroll
        for (int j = 0; j < 4; j++) acc[i][j] = 0ull;

    const float* __restrict__ qpBase = &g_qp[(size_t)b * TQ * H];
    const int ld_t0 = tid >> 1;            // loader: thread's base t (float4 idx)
    const int ld_c  = (tid & 1) * 4;

    // prologue: prefetch chunk 0 (2 float4/thread)
    float4 pre[2];
#pragma unroll
    for (int i = 0; i < 2; i++)
        pre[i] = *(const float4*)&qpBase[(ld_t0 + 256 * i) * H + ld_c];

    for (int kb = 0; kb < H / HC; kb++) {
        float* qb = (kb & 1) ? qpS1 : qpS0;
        const int hb = kb * HC;
        // commit prefetched chunk kb into buf
#pragma unroll
        for (int i = 0; i < 2; i++) {
            float* d = &qb[(ld_t0 + 256 * i) * QP + ld_c];
            d[0] = pre[i].x; d[1] = pre[i].y; d[2] = pre[i].z; d[3] = pre[i].w;
        }
        // prefetch chunk kb+1 (targets other buffer next iter)
        if (kb + 1 < H / HC) {
#pragma unroll
            for (int i = 0; i < 2; i++)
                pre[i] = *(const float4*)
                    &qpBase[(ld_t0 + 256 * i) * H + (kb + 1) * HC + ld_c];
        }
        __syncthreads();                   // buf committed by all; prev buf free
#pragma unroll
        for (int hl = 0; hl < HC; hl += 2) {
            const unsigned long long wvu = pk2(wvS[hb + hl], wvS[hb + hl + 1]);
            unsigned long long kvu[2], qvu[4];
#pragma unroll
            for (int i = 0; i < 2; i++)
                kvu[i] = pk2(kpS[g_kr + 4 * i][hb + hl],
                             kpS[g_kr + 4 * i][hb + hl + 1]);
#pragma unroll
            for (int j = 0; j < 4; j++)
                qvu[j] = pk2(qb[(g_t + 128 * j) * QP + hl],
                             qb[(g_t + 128 * j) * QP + hl + 1]);
#pragma unroll
            for (int i = 0; i < 2; i++)
#pragma unroll
                for (int j = 0; j < 4; j++) {
                    unsigned long long x2 = add2(kvu[i], qvu[j]);
                    float x0, x1, t0, t1;
                    upk2(x2, x0, x1);
                    asm("tanh.approx.f32 %0, %1;" : "=f"(t0) : "f"(x0));
                    asm("tanh.approx.f32 %0, %1;" : "=f"(t1) : "f"(x1));
                    fma2(acc[i][j], pk2(t0, t1), wvu);
                }
        }
    }
    // reduce packed halves, write scores (b_v omitted: softmax shift-invariant)
#pragma unroll
    for (int i = 0; i < 2; i++)
#pragma unroll
        for (int j = 0; j < 4; j++) {
            upk2(acc[i][j], acc_lo, acc_hi);
            attnS[g_kr + 4 * i][g_t + 128 * j] = acc_lo + acc_hi;
        }
    __syncthreads();

    // ---- phase 2: masked softmax, warp w (w<8) owns row w ----
    {
        const int wid = tid >> 5, lane = tid & 31;
        if (wid < KR) {
            const int row = wid;
            const int vl  = vlS[row];
            float m = -1e30f;
            for (int t = lane; t < TQ; t += 32) {
                float s = attnS[row][t];
                if (t < vl) m = fmaxf(m, s);
            }
#pragma unroll
            for (int o = 16; o; o >>= 1)
                m = fmaxf(m, __shfl_xor_sync(0xffffffffu, m, o));
            float sum = 0.f;
            for (int t = lane; t < TQ; t += 32) {
                float e = (t < vl) ? __expf(attnS[row][t] - m) : 0.f;
                attnS[row][t] = e;
                sum += e;
            }
#pragma unroll
            for (int o = 16; o; o >>= 1)
                sum += __shfl_xor_sync(0xffffffffu, sum, o);
            const float inv = 1.f / sum;
            for (int t = lane; t < TQ; t += 32) attnS[row][t] *= inv;
        }
    }
    __syncthreads();

    // ---- phase 3: out[kr][v] = sum_t attn[kr][t] * value[b][t][v] ----
    // thread = (v4, krq, th): 4 k-rows, t quarter. f32x2 FMAs.
    {
        const int v4  = tid & 63;          // float4 column 0..63
        const int grp = tid >> 6;          // 0..7
        const int krq = grp & 1;           // kr base = 4*krq
        const int th  = grp >> 1;          // t quarter 0..3
        const int t0  = th * (TQ / 4);

        unsigned long long oxy[4], ozw[4];
#pragma unroll
        for (int i = 0; i < 4; i++) { oxy[i] = 0ull; ozw[i] = 0ull; }

        const float4* __restrict__ val4 =
            (const float4*)&value[(size_t)b * TQ * VS];

        for (int t = t0; t < t0 + TQ / 4; t += 4) {
            float4 a4[4];
#pragma unroll
            for (int i = 0; i < 4; i++)
                a4[i] = *(const float4*)&attnS[4 * krq + i][t];   // broadcast
#pragma unroll
            for (int tt = 0; tt < 4; tt++) {
                const float4 v = val4[(t + tt) * (VS / 4) + v4];
                const unsigned long long vxy = pk2(v.x, v.y);
                const unsigned long long vzw = pk2(v.z, v.w);
#pragma unroll
                for (int i = 0; i < 4; i++) {
                    const float a = (tt == 0) ? a4[i].x :
                                    (tt == 1) ? a4[i].y :
                                    (tt == 2) ? a4[i].z : a4[i].w;
                    const unsigned long long au = pk2(a, a);
                    fma2(oxy[i], au, vxy);
                    fma2(ozw[i], au, vzw);
                }
            }
        }
        __syncthreads();                   // everyone done READING attnS
        // partials: th 0,1 -> attnS bytes; th 2,3 -> qpS bytes
        float4* p0 = (float4*)&attnS[0][0];     // 1024 float4
        float4* p1 = (float4*)qpS0;             // 1024 float4 (of 2304)
        float4* dst = (th < 2) ? p0 : p1;
        const int sub = th & 1;
#pragma unroll
        for (int i = 0; i < 4; i++) {
            float4 o;
            upk2(oxy[i], o.x, o.y);
            upk2(ozw[i], o.z, o.w);
            dst[(sub * 8 + 4 * krq + i) * 64 + v4] = o;
        }
        __syncthreads();
        // reduce 4 partials per (kr, v4) and store
        {
            const int kr = tid >> 6;       // 0..7
            const int vv = tid & 63;
            float4 r0 = p0[kr * 64 + vv];
            float4 r1 = p0[(8 + kr) * 64 + vv];
            float4 r2 = p1[kr * 64 + vv];
            float4 r3 = p1[(8 + kr) * 64 + vv];
            float4 r = make_float4(r0.x + r1.x + r2.x + r3.x,
                                   r0.y + r1.y + r2.y + r3.y,
                                   r0.z + r1.z + r2.z + r3.z,
                                   r0.w + r1.w + r2.w + r3.w);
            *(float4*)&out[(size_t)(b * TK + kt0 + kr) * VS + vv * 4] = r;
        }
    }
}

// ---------------------------------------------------------------------------
extern "C" void kernel_launch(void* const* d_in, const int* in_sizes, int n_in,
                              void* d_out, int out_size)
{
    const float* key        = (const float*)d_in[0];
    const float* que        = (const float*)d_in[1];
    const float* value      = (const float*)d_in[2];
    const float* W_k        = (const float*)d_in[3];
    const float* b_k        = (const float*)d_in[4];
    const float* W_q        = (const float*)d_in[5];
    const float* b_q        = (const float*)d_in[6];
    const float* w_v        = (const float*)d_in[7];
    // d_in[8] = b_v: unused (softmax shift-invariant)
    const int*   valid_lens = (const int*)d_in[9];
    float* out = (float*)d_out;

    // opt in to >48KB dynamic smem (idempotent; capture-safe)
    cudaFuncSetAttribute(attn_kernel,
                         cudaFuncAttributeMaxDynamicSharedMemorySize, SM_TOTAL);

    proj_kernel<<<256, 128>>>(key, que, W_k, b_k, W_q, b_q);
    attn_kernel<<<BB * TK / KR, 512, SM_TOTAL>>>(value, w_v, valid_lens, out);
}

// round 6
// speedup vs baseline: 1.4438x; 1.1393x over previous
#include <cuda_runtime.h>

#define BB 4
#define TK 512
#define TQ 512
#define KS 256     // KEYSIZE == QUESIZE
#define H  128
#define VS 256
#define KR 8       // k-rows per attn block

// scratch for projections (allocation-free rule: __device__ globals)
__device__ float g_kp[BB * TK * H];      // [b][t][h]
__device__ float g_qpT[BB * H * TQ];     // [b][h][t]  (transposed!)

// ---- f32x2 packed helpers (Blackwell) — used in phase 3 only --------------
__device__ __forceinline__ unsigned long long pk2(float x, float y) {
    unsigned long long r;
    asm("mov.b64 %0, {%1,%2};" : "=l"(r) : "f"(x), "f"(y));
    return r;
}
__device__ __forceinline__ void upk2(unsigned long long v, float& x, float& y) {
    asm("mov.b64 {%0,%1}, %2;" : "=f"(x), "=f"(y) : "l"(v));
}
__device__ __forceinline__ void fma2(unsigned long long& d,
                                     unsigned long long a,
                                     unsigned long long b) {
    asm("fma.rn.f32x2 %0, %1, %2, %0;" : "+l"(d) : "l"(a), "l"(b));
}
__device__ __forceinline__ float tanhap(float x) {
    float r;
    asm("tanh.approx.f32 %0, %1;" : "=f"(r) : "f"(x));
    return r;
}

// ---------------------------------------------------------------------------
// Projections. blocks [0,256): kp, 8 rows each, row-major out.
//              blocks [256,384): qp, 16 rows each, TRANSPOSED out (qpT[h][t]).
// 128 threads; thread = output h.
// ---------------------------------------------------------------------------
__global__ __launch_bounds__(128) void proj_kernel(
    const float* __restrict__ key, const float* __restrict__ que,
    const float* __restrict__ W_k, const float* __restrict__ b_k,
    const float* __restrict__ W_q, const float* __restrict__ b_q)
{
    __shared__ float Ws[32][H];            // 16KB (reused as transpose tile)
    __shared__ float Xs[16][33];

    const int tid = threadIdx.x;
    const bool isK = (blockIdx.x < 256);

    if (isK) {
        const int row0 = blockIdx.x * 8;   // global row in [0,2048)
        float acc[8];
#pragma unroll
        for (int r = 0; r < 8; r++) acc[r] = 0.f;
        for (int kc = 0; kc < KS; kc += 32) {
#pragma unroll
            for (int i = 0; i < 32; i++)
                Ws[i][tid] = W_k[(kc + i) * H + tid];
#pragma unroll
            for (int i = 0; i < 2; i++) {
                int idx = i * 128 + tid;
                int r = idx >> 5, c = idx & 31;
                Xs[r][c] = key[(row0 + r) * KS + kc + c];
            }
            __syncthreads();
#pragma unroll
            for (int c = 0; c < 32; c++) {
                float w = Ws[c][tid];
#pragma unroll
                for (int r = 0; r < 8; r++)
                    acc[r] = fmaf(Xs[r][c], w, acc[r]);
            }
            __syncthreads();
        }
        const float bb = b_k[tid];
#pragma unroll
        for (int r = 0; r < 8; r++)
            g_kp[(row0 + r) * H + tid] = acc[r] + bb;
    } else {
        const int row0 = (blockIdx.x - 256) * 16;  // global q row
        const int b = row0 >> 9;
        const int t0 = row0 & 511;
        float acc[16];
#pragma unroll
        for (int r = 0; r < 16; r++) acc[r] = 0.f;
        for (int kc = 0; kc < KS; kc += 32) {
#pragma unroll
            for (int i = 0; i < 32; i++)
                Ws[i][tid] = W_q[(kc + i) * H + tid];
#pragma unroll
            for (int i = 0; i < 4; i++) {
                int idx = i * 128 + tid;
                int r = idx >> 5, c = idx & 31;
                Xs[r][c] = que[(row0 + r) * KS + kc + c];
            }
            __syncthreads();
#pragma unroll
            for (int c = 0; c < 32; c++) {
                float w = Ws[c][tid];
#pragma unroll
                for (int r = 0; r < 16; r++)
                    acc[r] = fmaf(Xs[r][c], w, acc[r]);
            }
            __syncthreads();
        }
        // transpose through smem for coalesced qpT stores
        const float bb = b_q[tid];
        float* Ts = &Ws[0][0];             // [128][17] = 2176 floats, fits 4096
#pragma unroll
        for (int r = 0; r < 16; r++)
            Ts[tid * 17 + r] = acc[r] + bb;
        __syncthreads();
#pragma unroll
        for (int i = 0; i < 16; i++) {
            int idx = i * 128 + tid;       // 0..2047
            int h = idx >> 4, r = idx & 15;
            g_qpT[((size_t)b * H + h) * TQ + t0 + r] = Ts[h * 17 + r];
        }
    }
}

// ---------------------------------------------------------------------------
// Fused scores + masked softmax + attn@value.
// One block = 8 k-rows of one batch. 256 blocks, 512 threads.
// Phase 1: thread = one t column (t=tid); rows sorted by vl desc so each
// warp's live rows are a prefix -> barrier-free, mask-skipped tanh.
// ---------------------------------------------------------------------------
__global__ __launch_bounds__(512, 2) void attn_kernel(
    const float* __restrict__ value,
    const float* __restrict__ w_v,
    const int*   __restrict__ valid_lens,
    float*       __restrict__ out)
{
    __shared__ __align__(16) float kpS[KR][H];        // 4KB
    __shared__ __align__(16) float wvS[H];            // 512B
    __shared__ __align__(16) float attnS[KR][TQ];     // 16KB
    __shared__ __align__(16) float scr[16 * 64 * 4];  // 16KB (1024 float4)
    __shared__ int vlS[KR], ordS[KR], svlS[KR];

    const int tid = threadIdx.x;           // 0..511
    const int bid = blockIdx.x;            // 0..255
    const int b   = bid >> 6;
    const int kt0 = (bid & 63) * KR;

    // stage kp rows + w_v; tid 0 sorts rows by vl desc
#pragma unroll
    for (int i = 0; i < 2; i++) {
        int idx = i * 512 + tid;           // 0..1023
        int kr = idx >> 7, h = idx & 127;
        kpS[kr][h] = g_kp[(b * TK + kt0 + kr) * H + h];
    }
    if (tid < H) wvS[tid] = w_v[tid];
    if (tid == 0) {
        int v[KR], o[KR];
#pragma unroll
        for (int r = 0; r < KR; r++) { v[r] = valid_lens[b * TK + kt0 + r]; o[r] = r; }
        // insertion sort desc
#pragma unroll
        for (int i = 1; i < KR; i++) {
            int vv = v[i], oo = o[i], j = i;
            while (j > 0 && v[j - 1] < vv) { v[j] = v[j - 1]; o[j] = o[j - 1]; j--; }
            v[j] = vv; o[j] = oo;
        }
#pragma unroll
        for (int r = 0; r < KR; r++) {
            svlS[r] = v[r]; ordS[r] = o[r]; vlS[o[r]] = v[r];
        }
    }
    __syncthreads();

    // ---- phase 1: barrier-free scores ----
    {
        const int t  = tid;
        const int wb = tid & ~31;          // warp's t base
        int nl = 0;
#pragma unroll
        for (int i = 0; i < KR; i++) nl += (svlS[i] > wb);

        const float* __restrict__ qp0 = g_qpT + (size_t)b * H * TQ + t;

#pragma unroll
        for (int ri = 0; ri < KR; ri++) {
            if (nl > ri) {
                const int r = ordS[ri];
                const float* __restrict__ kr0 = kpS[r];
                float a = 0.f;
#pragma unroll 4
                for (int h = 0; h < H; h += 4) {
                    float q0 = qp0[(h + 0) * TQ];
                    float q1 = qp0[(h + 1) * TQ];
                    float q2 = qp0[(h + 2) * TQ];
                    float q3 = qp0[(h + 3) * TQ];
                    const float4 kv = *(const float4*)&kr0[h];
                    const float4 wv = *(const float4*)&wvS[h];
                    a = fmaf(tanhap(kv.x + q0), wv.x, a);
                    a = fmaf(tanhap(kv.y + q1), wv.y, a);
                    a = fmaf(tanhap(kv.z + q2), wv.z, a);
                    a = fmaf(tanhap(kv.w + q3), wv.w, a);
                }
                attnS[r][t] = a;           // dead (r,t) stay garbage; masked below
            }
        }
    }
    __syncthreads();

    // ---- phase 2: masked softmax, warp w (w<8) owns row w ----
    {
        const int wid = tid >> 5, lane = tid & 31;
        if (wid < KR) {
            const int row = wid;
            const int vl  = vlS[row];
            float m = -1e30f;
            for (int t = lane; t < vl; t += 32)
                m = fmaxf(m, attnS[row][t]);
#pragma unroll
            for (int o = 16; o; o >>= 1)
                m = fmaxf(m, __shfl_xor_sync(0xffffffffu, m, o));
            float sum = 0.f;
            for (int t = lane; t < TQ; t += 32) {
                float e = (t < vl) ? __expf(attnS[row][t] - m) : 0.f;
                attnS[row][t] = e;
                sum += e;
            }
#pragma unroll
            for (int o = 16; o; o >>= 1)
                sum += __shfl_xor_sync(0xffffffffu, sum, o);
            const float inv = 1.f / sum;
            for (int t = lane; t < vl; t += 32) attnS[row][t] *= inv;
        }
    }
    __syncthreads();

    // ---- phase 3: out[kr][v] = sum_t attn[kr][t] * value[b][t][v] ----
    // thread = (v4, krq, th): 4 k-rows, t quarter, f32x2 FMAs. Clip at max vl.
    {
        const int v4  = tid & 63;
        const int grp = tid >> 6;          // 0..7
        const int krq = grp & 1;           // kr base = 4*krq
        const int th  = grp >> 1;          // t quarter
        const int t0  = th * (TQ / 4);
        const int tmaxr = (svlS[0] + 3) & ~3;
        const int bound = (t0 + TQ / 4 < tmaxr) ? t0 + TQ / 4 : tmaxr;

        unsigned long long oxy[4], ozw[4];
#pragma unroll
        for (int i = 0; i < 4; i++) { oxy[i] = 0ull; ozw[i] = 0ull; }

        const float4* __restrict__ val4 =
            (const float4*)&value[(size_t)b * TQ * VS];

        for (int t = t0; t < bound; t += 4) {
            float4 a4[4];
#pragma unroll
            for (int i = 0; i < 4; i++)
                a4[i] = *(const float4*)&attnS[4 * krq + i][t];   // broadcast
#pragma unroll
            for (int tt = 0; tt < 4; tt++) {
                const float4 v = val4[(t + tt) * (VS / 4) + v4];
                const unsigned long long vxy = pk2(v.x, v.y);
                const unsigned long long vzw = pk2(v.z, v.w);
#pragma unroll
                for (int i = 0; i < 4; i++) {
                    const float a = (tt == 0) ? a4[i].x :
                                    (tt == 1) ? a4[i].y :
                                    (tt == 2) ? a4[i].z : a4[i].w;
                    const unsigned long long au = pk2(a, a);
                    fma2(oxy[i], au, vxy);
                    fma2(ozw[i], au, vzw);
                }
            }
        }
        __syncthreads();                   // everyone done READING attnS
        float4* p0 = (float4*)&attnS[0][0];     // 1024 float4
        float4* p1 = (float4*)scr;              // 1024 float4
        float4* dst = (th < 2) ? p0 : p1;
        const int sub = th & 1;
#pragma unroll
        for (int i = 0; i < 4; i++) {
            float4 o;
            upk2(oxy[i], o.x, o.y);
            upk2(ozw[i], o.z, o.w);
            dst[(sub * 8 + 4 * krq + i) * 64 + v4] = o;
        }
        __syncthreads();
        {
            const int kr = tid >> 6;       // 0..7
            const int vv = tid & 63;
            float4 r0 = p0[kr * 64 + vv];
            float4 r1 = p0[(8 + kr) * 64 + vv];
            float4 r2 = p1[kr * 64 + vv];
            float4 r3 = p1[(8 + kr) * 64 + vv];
            float4 r = make_float4(r0.x + r1.x + r2.x + r3.x,
                                   r0.y + r1.y + r2.y + r3.y,
                                   r0.z + r1.z + r2.z + r3.z,
                                   r0.w + r1.w + r2.w + r3.w);
            *(float4*)&out[(size_t)(b * TK + kt0 + kr) * VS + vv * 4] = r;
        }
    }
}

// ---------------------------------------------------------------------------
extern "C" void kernel_launch(void* const* d_in, const int* in_sizes, int n_in,
                              void* d_out, int out_size)
{
    const float* key        = (const float*)d_in[0];
    const float* que        = (const float*)d_in[1];
    const float* value      = (const float*)d_in[2];
    const float* W_k        = (const float*)d_in[3];
    const float* b_k        = (const float*)d_in[4];
    const float* W_q        = (const float*)d_in[5];
    const float* b_q        = (const float*)d_in[6];
    const float* w_v        = (const float*)d_in[7];
    // d_in[8] = b_v: unused (softmax shift-invariant)
    const int*   valid_lens = (const int*)d_in[9];
    float* out = (float*)d_out;

    proj_kernel<<<384, 128>>>(key, que, W_k, b_k, W_q, b_q);
    attn_kernel<<<BB * TK / KR, 512>>>(value, w_v, valid_lens, out);
}

// round 7
// speedup vs baseline: 1.5294x; 1.0593x over previous
#include <cuda_runtime.h>

#define BB 4
#define TK 512
#define TQ 512
#define KS 256     // KEYSIZE == QUESIZE
#define H  128
#define VS 256
#define KR 8       // k-rows per attn block

// scratch for projections (allocation-free rule: __device__ globals)
__device__ float g_kp[BB * TK * H];      // [b][t][h]
__device__ float g_qpT[BB * H * TQ];     // [b][h][t]  (transposed!)

// ---- f32x2 packed helpers (Blackwell) -------------------------------------
__device__ __forceinline__ unsigned long long pk2(float x, float y) {
    unsigned long long r;
    asm("mov.b64 %0, {%1,%2};" : "=l"(r) : "f"(x), "f"(y));
    return r;
}
__device__ __forceinline__ void upk2(unsigned long long v, float& x, float& y) {
    asm("mov.b64 {%0,%1}, %2;" : "=f"(x), "=f"(y) : "l"(v));
}
__device__ __forceinline__ void fma2(unsigned long long& d,
                                     unsigned long long a,
                                     unsigned long long b) {
    asm("fma.rn.f32x2 %0, %1, %2, %0;" : "+l"(d) : "l"(a), "l"(b));
}
__device__ __forceinline__ float tanhap(float x) {
    float r;
    asm("tanh.approx.f32 %0, %1;" : "=f"(r) : "f"(x));
    return r;
}

// ---------------------------------------------------------------------------
// Projections, f32x2 packed. 16 rows per block.
// blocks [0,128): kp rows (row-major out). blocks [128,256): qp rows
// (transposed out: qpT[h][t]). 128 threads; thread = output h.
// W staged transposed in smem so (c,c+1) weight pairs are contiguous.
// ---------------------------------------------------------------------------
__global__ __launch_bounds__(128) void proj_kernel(
    const float* __restrict__ key, const float* __restrict__ que,
    const float* __restrict__ W_k, const float* __restrict__ b_k,
    const float* __restrict__ W_q, const float* __restrict__ b_q)
{
    __shared__ __align__(16) float sbuf[128 * 34];   // WsT[h][c] / Ts transpose
    __shared__ __align__(16) float Xs[16][34];

    const int tid = threadIdx.x;           // == output h
    const bool isK = (blockIdx.x < 128);
    const int row0 = (blockIdx.x & 127) * 16;
    const float* __restrict__ X = isK ? key : que;
    const float* __restrict__ W = isK ? W_k : W_q;
    const float* __restrict__ bias = isK ? b_k : b_q;

    unsigned long long acc2[16];
#pragma unroll
    for (int r = 0; r < 16; r++) acc2[r] = 0ull;

    for (int kc = 0; kc < KS; kc += 32) {
        // WsT[tid][c] = W[(kc+c)*H + tid]  (coalesced LDG, own-row STS)
#pragma unroll
        for (int c = 0; c < 32; c++)
            sbuf[tid * 34 + c] = W[(kc + c) * H + tid];
#pragma unroll
        for (int i = 0; i < 4; i++) {
            int idx = i * 128 + tid;       // 0..511
            int r = idx >> 5, c = idx & 31;
            Xs[r][c] = X[(row0 + r) * KS + kc + c];
        }
        __syncthreads();
#pragma unroll
        for (int cp = 0; cp < 16; cp++) {
            const float2 w2 = *(const float2*)&sbuf[tid * 34 + 2 * cp];
            const unsigned long long wu = pk2(w2.x, w2.y);
#pragma unroll
            for (int r = 0; r < 16; r++) {
                const float2 x2 = *(const float2*)&Xs[r][2 * cp];  // broadcast
                fma2(acc2[r], pk2(x2.x, x2.y), wu);
            }
        }
        __syncthreads();
    }

    const float bb = bias[tid];
    float acc[16];
#pragma unroll
    for (int r = 0; r < 16; r++) {
        float lo, hi;
        upk2(acc2[r], lo, hi);
        acc[r] = lo + hi + bb;
    }

    if (isK) {
#pragma unroll
        for (int r = 0; r < 16; r++)
            g_kp[(row0 + r) * H + tid] = acc[r];
    } else {
        // transpose through smem (reuse sbuf as Ts[h][r], stride 17)
        const int b  = row0 >> 9;
        const int t0 = row0 & 511;
#pragma unroll
        for (int r = 0; r < 16; r++)
            sbuf[tid * 17 + r] = acc[r];
        __syncthreads();
#pragma unroll
        for (int i = 0; i < 16; i++) {
            int idx = i * 128 + tid;       // 0..2047
            int h = idx >> 4, r = idx & 15;
            g_qpT[((size_t)b * H + h) * TQ + t0 + r] = sbuf[h * 17 + r];
        }
    }
}

// ---------------------------------------------------------------------------
// Fused scores + masked softmax + attn@value.
// One block = 8 k-rows of one batch. 256 blocks, 512 threads (single wave).
// Phase 1: worklist of live (row, 32-col tile) items, consumed round-robin
// by the 16 warps -> balanced, barrier-free, mask-skipped.
// ---------------------------------------------------------------------------
__global__ __launch_bounds__(512, 2) void attn_kernel(
    const float* __restrict__ value,
    const float* __restrict__ w_v,
    const int*   __restrict__ valid_lens,
    float*       __restrict__ out)
{
    __shared__ __align__(16) float kpS[KR][H];        // 4KB
    __shared__ __align__(16) float wvS[H];            // 512B
    __shared__ __align__(16) float attnS[KR][TQ];     // 16KB
    __shared__ __align__(16) float scr[16 * 64 * 4];  // 16KB (1024 float4)
    __shared__ int vlS[KR];
    __shared__ int wl[KR * 16];                       // item = r*16 + tile
    __shared__ int nItS, maxVlS;

    const int tid  = threadIdx.x;          // 0..511
    const int wid  = tid >> 5;
    const int lane = tid & 31;
    const int bid  = blockIdx.x;           // 0..255
    const int b    = bid >> 6;
    const int kt0  = (bid & 63) * KR;

    // stage kp rows + w_v; tid 0 builds worklist
#pragma unroll
    for (int i = 0; i < 2; i++) {
        int idx = i * 512 + tid;           // 0..1023
        int kr = idx >> 7, h = idx & 127;
        kpS[kr][h] = g_kp[(b * TK + kt0 + kr) * H + h];
    }
    if (tid < H) wvS[tid] = w_v[tid];
    if (tid == 0) {
        int n = 0, mx = 0;
#pragma unroll
        for (int r = 0; r < KR; r++) {
            const int vl = valid_lens[b * TK + kt0 + r];
            vlS[r] = vl;
            if (vl > mx) mx = vl;
            const int nt = (vl + 31) >> 5;
            for (int tile = 0; tile < nt; tile++)
                wl[n++] = r * 16 + tile;
        }
        nItS = n;
        maxVlS = mx;
    }
    __syncthreads();

    // ---- phase 1: balanced, barrier-free scores ----
    {
        const int nIt = nItS;
        const float* __restrict__ qpB = g_qpT + (size_t)b * H * TQ;
        for (int it = wid; it < nIt; it += 16) {
            const int e = wl[it];
            const int r = e >> 4;
            const int col = (e & 15) * 32 + lane;
            const float* __restrict__ qp0 = qpB + col;
            const float* __restrict__ kr0 = kpS[r];
            float a = 0.f;
#pragma unroll 4
            for (int h = 0; h < H; h += 4) {
                float q0 = qp0[(h + 0) * TQ];
                float q1 = qp0[(h + 1) * TQ];
                float q2 = qp0[(h + 2) * TQ];
                float q3 = qp0[(h + 3) * TQ];
                const float4 kv = *(const float4*)&kr0[h];
                const float4 wv = *(const float4*)&wvS[h];
                a = fmaf(tanhap(kv.x + q0), wv.x, a);
                a = fmaf(tanhap(kv.y + q1), wv.y, a);
                a = fmaf(tanhap(kv.z + q2), wv.z, a);
                a = fmaf(tanhap(kv.w + q3), wv.w, a);
            }
            attnS[r][col] = a;             // cols >= vl garbage; masked below
        }
    }
    __syncthreads();

    // ---- phase 2: masked softmax, warp w (w<8) owns row w ----
    if (wid < KR) {
        const int row = wid;
        const int vl  = vlS[row];
        float m = -1e30f;
        for (int t = lane; t < vl; t += 32)
            m = fmaxf(m, attnS[row][t]);
#pragma unroll
        for (int o = 16; o; o >>= 1)
            m = fmaxf(m, __shfl_xor_sync(0xffffffffu, m, o));
        float sum = 0.f;
        for (int t = lane; t < TQ; t += 32) {
            float e = (t < vl) ? __expf(attnS[row][t] - m) : 0.f;
            attnS[row][t] = e;
            sum += e;
        }
#pragma unroll
        for (int o = 16; o; o >>= 1)
            sum += __shfl_xor_sync(0xffffffffu, sum, o);
        const float inv = 1.f / sum;
        for (int t = lane; t < vl; t += 32) attnS[row][t] *= inv;
    }
    __syncthreads();

    // ---- phase 3: out[kr][v] = sum_t attn[kr][t] * value[b][t][v] ----
    {
        const int v4  = tid & 63;
        const int grp = tid >> 6;          // 0..7
        const int krq = grp & 1;           // kr base = 4*krq
        const int th  = grp >> 1;          // t quarter
        const int t0  = th * (TQ / 4);
        const int tmaxr = (maxVlS + 3) & ~3;
        const int bound = (t0 + TQ / 4 < tmaxr) ? t0 + TQ / 4 : tmaxr;

        unsigned long long oxy[4], ozw[4];
#pragma unroll
        for (int i = 0; i < 4; i++) { oxy[i] = 0ull; ozw[i] = 0ull; }

        const float4* __restrict__ val4 =
            (const float4*)&value[(size_t)b * TQ * VS];

        for (int t = t0; t < bound; t += 4) {
            float4 a4[4];
#pragma unroll
            for (int i = 0; i < 4; i++)
                a4[i] = *(const float4*)&attnS[4 * krq + i][t];   // broadcast
#pragma unroll
            for (int tt = 0; tt < 4; tt++) {
                const float4 v = val4[(t + tt) * (VS / 4) + v4];
                const unsigned long long vxy = pk2(v.x, v.y);
                const unsigned long long vzw = pk2(v.z, v.w);
#pragma unroll
                for (int i = 0; i < 4; i++) {
                    const float a = (tt == 0) ? a4[i].x :
                                    (tt == 1) ? a4[i].y :
                                    (tt == 2) ? a4[i].z : a4[i].w;
                    const unsigned long long au = pk2(a, a);
                    fma2(oxy[i], au, vxy);
                    fma2(ozw[i], au, vzw);
                }
            }
        }
        __syncthreads();                   // everyone done READING attnS
        float4* p0 = (float4*)&attnS[0][0];     // 1024 float4
        float4* p1 = (float4*)scr;              // 1024 float4
        float4* dst = (th < 2) ? p0 : p1;
        const int sub = th & 1;
#pragma unroll
        for (int i = 0; i < 4; i++) {
            float4 o;
            upk2(oxy[i], o.x, o.y);
            upk2(ozw[i], o.z, o.w);
            dst[(sub * 8 + 4 * krq + i) * 64 + v4] = o;
        }
        __syncthreads();
        {
            const int kr = tid >> 6;       // 0..7
            const int vv = tid & 63;
            float4 r0 = p0[kr * 64 + vv];
            float4 r1 = p0[(8 + kr) * 64 + vv];
            float4 r2 = p1[kr * 64 + vv];
            float4 r3 = p1[(8 + kr) * 64 + vv];
            float4 r = make_float4(r0.x + r1.x + r2.x + r3.x,
                                   r0.y + r1.y + r2.y + r3.y,
                                   r0.z + r1.z + r2.z + r3.z,
                                   r0.w + r1.w + r2.w + r3.w);
            *(float4*)&out[(size_t)(b * TK + kt0 + kr) * VS + vv * 4] = r;
        }
    }
}

// ---------------------------------------------------------------------------
extern "C" void kernel_launch(void* const* d_in, const int* in_sizes, int n_in,
                              void* d_out, int out_size)
{
    const float* key        = (const float*)d_in[0];
    const float* que        = (const float*)d_in[1];
    const float* value      = (const float*)d_in[2];
    const float* W_k        = (const float*)d_in[3];
    const float* b_k        = (const float*)d_in[4];
    const float* W_q        = (const float*)d_in[5];
    const float* b_q        = (const float*)d_in[6];
    const float* w_v        = (const float*)d_in[7];
    // d_in[8] = b_v: unused (softmax shift-invariant)
    const int*   valid_lens = (const int*)d_in[9];
    float* out = (float*)d_out;

    proj_kernel<<<256, 128>>>(key, que, W_k, b_k, W_q, b_q);
    attn_kernel<<<BB * TK / KR, 512>>>(value, w_v, valid_lens, out);
}